// round 10
// baseline (speedup 1.0000x reference)
#include <cuda_runtime.h>
#include <cuda_fp16.h>
#include <cstdint>

#define NN 50000
#define NE 800000
#define F  128
#define SCAN_B 256
#define NBLK ((NN + SCAN_B - 1) / SCAN_B)   // 196

#define BM   64           // gemm rows per block
#define GT   128          // gemm threads
#define SW   132          // Hs padded row stride (floats)
#define WPAD 17           // Wpk padded nt stride (uint4s)
#define KSP  8            // k-steps of 16

// ---------------- device scratch (no allocations allowed) -------------------
__device__ int    g_deg_out_i[NN];
__device__ int    g_deg_in_i[NN];
__device__ int    g_row_start[NN];
__device__ float  g_scale_out[NN];
__device__ int    g_slot[NE];
__device__ int    g_perm_src[NE];
__device__ __half g_xh[NN * F];            // fp16 copy of x (gather payload)
__device__ float  g_h[NN * F];
__device__ uint4  g_Wpk[KSP * 32 * 16];    // fp16 frags {bh0,bh1,bl0,bl1}
__device__ int    g_scan_tmp[NN];
__device__ int    g_block_sums[NBLK];

__device__ __forceinline__ uint32_t h2u(half2 h) {
    return *reinterpret_cast<uint32_t*>(&h);
}

// ---------------------------------------------------------------------------
// 1) init: zero degrees + fp16-split fragment W + convert x -> fp16
//    grid covers NN*F/8 (each thread converts 8 floats)
// ---------------------------------------------------------------------------
__global__ void init_kernel(const float* __restrict__ x,
                            const float* __restrict__ weight) {
    int i = blockIdx.x * blockDim.x + threadIdx.x;
    if (i < NN) { g_deg_out_i[i] = 0; g_deg_in_i[i] = 0; }
    if (i < KSP * 32 * 16) {
        int nt   = i & 15;
        int rest = i >> 4;
        int lane = rest & 31;
        int ks   = rest >> 5;
        int t    = lane & 3;
        int g    = lane >> 2;
        int k0 = ks * 16, n0 = nt * 8;
        float w00 = weight[(k0 + 2 * t)     * F + n0 + g];
        float w01 = weight[(k0 + 2 * t + 1) * F + n0 + g];
        float w10 = weight[(k0 + 2 * t + 8) * F + n0 + g];
        float w11 = weight[(k0 + 2 * t + 9) * F + n0 + g];
        half2 h0 = __floats2half2_rn(w00, w01);
        half2 h1 = __floats2half2_rn(w10, w11);
        half2 l0 = __floats2half2_rn(w00 - __half2float(__low2half(h0)),
                                     w01 - __half2float(__high2half(h0)));
        half2 l1 = __floats2half2_rn(w10 - __half2float(__low2half(h1)),
                                     w11 - __half2float(__high2half(h1)));
        g_Wpk[i] = make_uint4(h2u(h0), h2u(h1), h2u(l0), h2u(l1));
    }
    if (i < NN * F / 8) {
        const float4* x4 = reinterpret_cast<const float4*>(x);
        float4 a = x4[i * 2];
        float4 b = x4[i * 2 + 1];
        uint4 o;
        o.x = h2u(__floats2half2_rn(a.x, a.y));
        o.y = h2u(__floats2half2_rn(a.z, a.w));
        o.z = h2u(__floats2half2_rn(b.x, b.y));
        o.w = h2u(__floats2half2_rn(b.z, b.w));
        reinterpret_cast<uint4*>(g_xh)[i] = o;
    }
}

// ---------------------------------------------------------------------------
// 2) degrees; in-degree atomic return value = edge slot
// ---------------------------------------------------------------------------
__global__ void deg_kernel(const int* __restrict__ src, const int* __restrict__ dst) {
    int t = blockIdx.x * blockDim.x + threadIdx.x;
    int e0 = t * 2;
    if (e0 < NE) {
        int s0 = src[e0], s1 = src[e0 + 1];
        int d0 = dst[e0], d1 = dst[e0 + 1];
        atomicAdd(&g_deg_out_i[s0], 1);
        atomicAdd(&g_deg_out_i[s1], 1);
        g_slot[e0]     = atomicAdd(&g_deg_in_i[d0], 1);
        g_slot[e0 + 1] = atomicAdd(&g_deg_in_i[d1], 1);
    }
}

// ---------------------------------------------------------------------------
// 3a) per-block exclusive scan of deg_in
// ---------------------------------------------------------------------------
__global__ void __launch_bounds__(SCAN_B)
scan1_kernel() {
    int idx  = blockIdx.x * SCAN_B + threadIdx.x;
    int lane = threadIdx.x & 31;
    int w    = threadIdx.x >> 5;
    int v    = (idx < NN) ? g_deg_in_i[idx] : 0;
    int x = v;
#pragma unroll
    for (int o = 1; o < 32; o <<= 1) {
        int t = __shfl_up_sync(0xffffffffu, x, o);
        if (lane >= o) x += t;
    }
    __shared__ int wsum[8];
    if (lane == 31) wsum[w] = x;
    __syncthreads();
    if (threadIdx.x < 8) {
        int s = wsum[threadIdx.x];
#pragma unroll
        for (int o = 1; o < 8; o <<= 1) {
            int t = __shfl_up_sync(0xffu, s, o);
            if ((int)threadIdx.x >= o) s += t;
        }
        wsum[threadIdx.x] = s;
    }
    __syncthreads();
    int woff = (w > 0) ? wsum[w - 1] : 0;
    if (idx < NN) g_scan_tmp[idx] = woff + x - v;
    if (threadIdx.x == SCAN_B - 1) g_block_sums[blockIdx.x] = wsum[7];
}

// ---------------------------------------------------------------------------
// 3b) apply: each block reduces its preceding block sums itself
// ---------------------------------------------------------------------------
__global__ void __launch_bounds__(SCAN_B)
scan3_kernel() {
    int bid  = blockIdx.x;
    int t    = threadIdx.x;
    int lane = t & 31;
    int w    = t >> 5;
    int v = (t < bid && t < NBLK) ? g_block_sums[t] : 0;   // NBLK <= 256
#pragma unroll
    for (int o = 16; o > 0; o >>= 1) v += __shfl_down_sync(0xffffffffu, v, o);
    __shared__ int wsum[8];
    __shared__ int s_base;
    if (lane == 0) wsum[w] = v;
    __syncthreads();
    if (t == 0) {
        int s = 0;
#pragma unroll
        for (int j = 0; j < 8; j++) s += wsum[j];
        s_base = s;
    }
    __syncthreads();
    int idx = bid * SCAN_B + t;
    if (idx < NN) {
        g_row_start[idx] = g_scan_tmp[idx] + s_base;
        g_scale_out[idx] = rsqrtf(fmaxf((float)g_deg_out_i[idx], 1.0f));
    }
}

// ---------------------------------------------------------------------------
// 4) atomic-free scatter: perm[row_start[dst] + slot] = src
// ---------------------------------------------------------------------------
__global__ void scatter_kernel(const int* __restrict__ src, const int* __restrict__ dst) {
    int t = blockIdx.x * blockDim.x + threadIdx.x;
    int e0 = t * 4;
    if (e0 < NE) {
        int4 d  = *reinterpret_cast<const int4*>(dst + e0);
        int4 s  = *reinterpret_cast<const int4*>(src + e0);
        int4 sl = *reinterpret_cast<const int4*>(g_slot + e0);
        g_perm_src[g_row_start[d.x] + sl.x] = s.x;
        g_perm_src[g_row_start[d.y] + sl.y] = s.y;
        g_perm_src[g_row_start[d.z] + sl.z] = s.z;
        g_perm_src[g_row_start[d.w] + sl.w] = s.w;
    }
}

// ---------------------------------------------------------------------------
// 5) CSR aggregation over fp16 x: one warp per node; fp32 accumulate.
//    Lane reads uint2 (4 halves = features 4l..4l+3); 256B/row coalesced.
// ---------------------------------------------------------------------------
__global__ void __launch_bounds__(256)
agg_kernel() {
    int gtid = blockIdx.x * blockDim.x + threadIdx.x;
    int node = gtid >> 5;
    int lane = threadIdx.x & 31;
    if (node >= NN) return;

    int start = g_row_start[node];
    int len   = g_deg_in_i[node];
    const int* ps = g_perm_src + start;
    const uint2* xh = reinterpret_cast<const uint2*>(g_xh);   // row = 32 uint2

    float4 acc = make_float4(0.f, 0.f, 0.f, 0.f);
    int i = 0;
    for (; i + 4 <= len; i += 4) {
        int s0 = ps[i], s1 = ps[i + 1], s2 = ps[i + 2], s3 = ps[i + 3];
        float c0 = g_scale_out[s0], c1 = g_scale_out[s1];
        float c2 = g_scale_out[s2], c3 = g_scale_out[s3];
        uint2 r0 = xh[(size_t)s0 * 32 + lane];
        uint2 r1 = xh[(size_t)s1 * 32 + lane];
        uint2 r2 = xh[(size_t)s2 * 32 + lane];
        uint2 r3 = xh[(size_t)s3 * 32 + lane];
        float2 a0 = __half22float2(*reinterpret_cast<half2*>(&r0.x));
        float2 b0 = __half22float2(*reinterpret_cast<half2*>(&r0.y));
        float2 a1 = __half22float2(*reinterpret_cast<half2*>(&r1.x));
        float2 b1 = __half22float2(*reinterpret_cast<half2*>(&r1.y));
        float2 a2 = __half22float2(*reinterpret_cast<half2*>(&r2.x));
        float2 b2 = __half22float2(*reinterpret_cast<half2*>(&r2.y));
        float2 a3 = __half22float2(*reinterpret_cast<half2*>(&r3.x));
        float2 b3 = __half22float2(*reinterpret_cast<half2*>(&r3.y));
        acc.x += c0 * a0.x; acc.y += c0 * a0.y; acc.z += c0 * b0.x; acc.w += c0 * b0.y;
        acc.x += c1 * a1.x; acc.y += c1 * a1.y; acc.z += c1 * b1.x; acc.w += c1 * b1.y;
        acc.x += c2 * a2.x; acc.y += c2 * a2.y; acc.z += c2 * b2.x; acc.w += c2 * b2.y;
        acc.x += c3 * a3.x; acc.y += c3 * a3.y; acc.z += c3 * b3.x; acc.w += c3 * b3.y;
    }
    for (; i < len; i++) {
        int s0 = ps[i];
        float c0 = g_scale_out[s0];
        uint2 r0 = xh[(size_t)s0 * 32 + lane];
        float2 a0 = __half22float2(*reinterpret_cast<half2*>(&r0.x));
        float2 b0 = __half22float2(*reinterpret_cast<half2*>(&r0.y));
        acc.x += c0 * a0.x; acc.y += c0 * a0.y; acc.z += c0 * b0.x; acc.w += c0 * b0.y;
    }
    float inv = rsqrtf(fmaxf((float)len, 1.0f));
    acc.x *= inv; acc.y *= inv; acc.z *= inv; acc.w *= inv;
    reinterpret_cast<float4*>(g_h + (size_t)node * F)[lane] = acc;
}

// ---------------------------------------------------------------------------
// 6) GEMM via 2-way fp16-split HMMA m16n8k16: out = h @ W + bias (R8-proven)
// ---------------------------------------------------------------------------
__device__ __forceinline__ void mma_f16(float& d0, float& d1, float& d2, float& d3,
                                        uint32_t a0, uint32_t a1, uint32_t a2, uint32_t a3,
                                        uint32_t b0, uint32_t b1) {
    asm volatile(
        "mma.sync.aligned.m16n8k16.row.col.f32.f16.f16.f32 "
        "{%0,%1,%2,%3}, {%4,%5,%6,%7}, {%8,%9}, {%0,%1,%2,%3};"
        : "+f"(d0), "+f"(d1), "+f"(d2), "+f"(d3)
        : "r"(a0), "r"(a1), "r"(a2), "r"(a3), "r"(b0), "r"(b1));
}

__device__ __forceinline__ void split2(float2 f, uint32_t& hi, uint32_t& lo) {
    half2 h = __floats2half2_rn(f.x, f.y);
    half2 l = __floats2half2_rn(f.x - __half2float(__low2half(h)),
                                f.y - __half2float(__high2half(h)));
    hi = h2u(h); lo = h2u(l);
}

__global__ void __launch_bounds__(GT, 2)
gemm_tc_kernel(const float* __restrict__ bias, float* __restrict__ out) {
    extern __shared__ float sm[];
    uint4* Wps = reinterpret_cast<uint4*>(sm);          // KSP*32*17 uint4
    float* Hs  = sm + KSP * 32 * WPAD * 4;              // BM * SW floats
    float* Bs  = Hs + BM * SW;                          // F floats

    int tid  = threadIdx.x;
    int row0 = blockIdx.x * BM;

    for (int i = tid; i < KSP * 32 * 16; i += GT) {
        int nt = i & 15, rest = i >> 4;
        Wps[rest * WPAD + nt] = g_Wpk[i];
    }
    for (int i = tid; i < BM * (F / 4); i += GT) {
        int r = i / (F / 4), c4 = i % (F / 4);
        float4 v = make_float4(0.f, 0.f, 0.f, 0.f);
        int grow = row0 + r;
        if (grow < NN)
            v = reinterpret_cast<const float4*>(g_h)[grow * (F / 4) + c4];
        reinterpret_cast<float4*>(&Hs[r * SW + c4 * 4])[0] = v;
    }
    if (tid < F) Bs[tid] = bias[tid];
    __syncthreads();

    int warp = tid >> 5;
    int lane = tid & 31;
    int g    = lane >> 2;
    int t    = lane & 3;
    int rb   = warp * 16;

    float d[16][4];
#pragma unroll
    for (int nt = 0; nt < 16; nt++)
#pragma unroll
        for (int j = 0; j < 4; j++) d[nt][j] = 0.f;

#pragma unroll
    for (int ks = 0; ks < KSP; ks++) {
        int k0 = ks * 16;
        float2 f00 = *reinterpret_cast<float2*>(&Hs[(rb + g)     * SW + k0 + 2 * t]);
        float2 f10 = *reinterpret_cast<float2*>(&Hs[(rb + g + 8) * SW + k0 + 2 * t]);
        float2 f01 = *reinterpret_cast<float2*>(&Hs[(rb + g)     * SW + k0 + 2 * t + 8]);
        float2 f11 = *reinterpret_cast<float2*>(&Hs[(rb + g + 8) * SW + k0 + 2 * t + 8]);
        uint32_t ah0, al0, ah1, al1, ah2, al2, ah3, al3;
        split2(f00, ah0, al0);
        split2(f10, ah1, al1);
        split2(f01, ah2, al2);
        split2(f11, ah3, al3);

        const uint4* wrow = &Wps[(ks * 32 + lane) * WPAD];
#pragma unroll
        for (int nt = 0; nt < 16; nt++) {
            uint4 wb = wrow[nt];
            mma_f16(d[nt][0], d[nt][1], d[nt][2], d[nt][3],
                    ah0, ah1, ah2, ah3, wb.x, wb.y);       // Ah*Bh
            mma_f16(d[nt][0], d[nt][1], d[nt][2], d[nt][3],
                    ah0, ah1, ah2, ah3, wb.z, wb.w);       // Ah*Bl
            mma_f16(d[nt][0], d[nt][1], d[nt][2], d[nt][3],
                    al0, al1, al2, al3, wb.x, wb.y);       // Al*Bh
        }
    }

    int rA = row0 + rb + g;
    int rB = rA + 8;
#pragma unroll
    for (int nt = 0; nt < 16; nt++) {
        int col = nt * 8 + t * 2;
        float b0 = Bs[col], b1 = Bs[col + 1];
        if (rA < NN) {
            float2 o = make_float2(d[nt][0] + b0, d[nt][1] + b1);
            reinterpret_cast<float2*>(out + (size_t)rA * F + col)[0] = o;
        }
        if (rB < NN) {
            float2 o = make_float2(d[nt][2] + b0, d[nt][3] + b1);
            reinterpret_cast<float2*>(out + (size_t)rB * F + col)[0] = o;
        }
    }
}

// ---------------------------------------------------------------------------
extern "C" void kernel_launch(void* const* d_in, const int* in_sizes, int n_in,
                              void* d_out, int out_size) {
    const float* x      = (const float*)d_in[0];
    const int*   src    = (const int*)d_in[1];
    const int*   dst    = (const int*)d_in[2];
    const float* weight = (const float*)d_in[3];
    const float* bias   = (const float*)d_in[4];
    float*       out    = (float*)d_out;

    init_kernel<<<(NN * F / 8 + 255) / 256, 256>>>(x, weight);
    deg_kernel<<<(NE / 2 + 255) / 256, 256>>>(src, dst);
    scan1_kernel<<<NBLK, SCAN_B>>>();
    scan3_kernel<<<NBLK, SCAN_B>>>();
    scatter_kernel<<<(NE / 4 + 255) / 256, 256>>>(src, dst);

    {
        long long threads = (long long)NN * 32;
        int blocks = (int)((threads + 255) / 256);
        agg_kernel<<<blocks, 256>>>();
    }
    {
        int smem = (KSP * 32 * WPAD * 4 + BM * SW + F) * (int)sizeof(float); // 103936 B
        cudaFuncSetAttribute(gemm_tc_kernel, cudaFuncAttributeMaxDynamicSharedMemorySize, smem);
        gemm_tc_kernel<<<(NN + BM - 1) / BM, GT, smem>>>(bias, out);
    }
}

// round 13
// speedup vs baseline: 1.0258x; 1.0258x over previous
#include <cuda_runtime.h>
#include <cuda_fp16.h>
#include <cstdint>

#define NN 50000
#define NE 800000
#define F  128
#define SCAN_B 256
#define NBLK ((NN + SCAN_B - 1) / SCAN_B)   // 196

#define BM   64           // gemm rows per block
#define GT   128          // gemm threads
#define SW   132          // Hs padded row stride (floats)
#define WPAD 17           // Wpk padded nt stride (uint4s)
#define KSP  8            // k-steps of 16

// ---------------- device scratch (no allocations allowed) -------------------
__device__ int   g_deg_out_i[NN];
__device__ int   g_deg_in_i[NN];
__device__ int   g_row_start[NN];
__device__ float g_scale_out[NN];
__device__ int   g_slot[NE];
__device__ int   g_perm_src[NE + 8];       // +pad so int4 tail reads are safe
__device__ float g_h[NN * F];
__device__ uint4 g_Wpk[KSP * 32 * 16];     // fp16 frags {bh0,bh1,bl0,bl1}
__device__ int   g_scan_tmp[NN];
__device__ int   g_block_sums[NBLK];

__device__ __forceinline__ uint32_t h2u(half2 h) {
    return *reinterpret_cast<uint32_t*>(&h);
}

// ---------------------------------------------------------------------------
// 1) init: zero degrees + fp16-split fragment-ordered W (R8 version)
// ---------------------------------------------------------------------------
__global__ void init_kernel(const float* __restrict__ weight) {
    int i = blockIdx.x * blockDim.x + threadIdx.x;
    if (i < NN) { g_deg_out_i[i] = 0; g_deg_in_i[i] = 0; }
    if (i < KSP * 32 * 16) {
        int nt   = i & 15;
        int rest = i >> 4;
        int lane = rest & 31;
        int ks   = rest >> 5;
        int t    = lane & 3;
        int g    = lane >> 2;
        int k0 = ks * 16, n0 = nt * 8;
        float w00 = weight[(k0 + 2 * t)     * F + n0 + g];
        float w01 = weight[(k0 + 2 * t + 1) * F + n0 + g];
        float w10 = weight[(k0 + 2 * t + 8) * F + n0 + g];
        float w11 = weight[(k0 + 2 * t + 9) * F + n0 + g];
        half2 h0 = __floats2half2_rn(w00, w01);
        half2 h1 = __floats2half2_rn(w10, w11);
        half2 l0 = __floats2half2_rn(w00 - __half2float(__low2half(h0)),
                                     w01 - __half2float(__high2half(h0)));
        half2 l1 = __floats2half2_rn(w10 - __half2float(__low2half(h1)),
                                     w11 - __half2float(__high2half(h1)));
        g_Wpk[i] = make_uint4(h2u(h0), h2u(h1), h2u(l0), h2u(l1));
    }
}

// ---------------------------------------------------------------------------
// 2) degrees; in-degree atomic return value = edge slot
// ---------------------------------------------------------------------------
__global__ void deg_kernel(const int* __restrict__ src, const int* __restrict__ dst) {
    int t = blockIdx.x * blockDim.x + threadIdx.x;
    int e0 = t * 2;
    if (e0 < NE) {
        int s0 = src[e0], s1 = src[e0 + 1];
        int d0 = dst[e0], d1 = dst[e0 + 1];
        atomicAdd(&g_deg_out_i[s0], 1);
        atomicAdd(&g_deg_out_i[s1], 1);
        g_slot[e0]     = atomicAdd(&g_deg_in_i[d0], 1);
        g_slot[e0 + 1] = atomicAdd(&g_deg_in_i[d1], 1);
    }
}

// ---------------------------------------------------------------------------
// 3a) per-block exclusive scan of deg_in
// ---------------------------------------------------------------------------
__global__ void __launch_bounds__(SCAN_B)
scan1_kernel() {
    int idx  = blockIdx.x * SCAN_B + threadIdx.x;
    int lane = threadIdx.x & 31;
    int w    = threadIdx.x >> 5;
    int v    = (idx < NN) ? g_deg_in_i[idx] : 0;
    int x = v;
#pragma unroll
    for (int o = 1; o < 32; o <<= 1) {
        int t = __shfl_up_sync(0xffffffffu, x, o);
        if (lane >= o) x += t;
    }
    __shared__ int wsum[8];
    if (lane == 31) wsum[w] = x;
    __syncthreads();
    if (threadIdx.x < 8) {
        int s = wsum[threadIdx.x];
#pragma unroll
        for (int o = 1; o < 8; o <<= 1) {
            int t = __shfl_up_sync(0xffu, s, o);
            if ((int)threadIdx.x >= o) s += t;
        }
        wsum[threadIdx.x] = s;
    }
    __syncthreads();
    int woff = (w > 0) ? wsum[w - 1] : 0;
    if (idx < NN) g_scan_tmp[idx] = woff + x - v;
    if (threadIdx.x == SCAN_B - 1) g_block_sums[blockIdx.x] = wsum[7];
}

// ---------------------------------------------------------------------------
// 3b) apply: each block reduces its preceding block sums itself
// ---------------------------------------------------------------------------
__global__ void __launch_bounds__(SCAN_B)
scan3_kernel() {
    int bid  = blockIdx.x;
    int t    = threadIdx.x;
    int lane = t & 31;
    int w    = t >> 5;
    int v = (t < bid && t < NBLK) ? g_block_sums[t] : 0;   // NBLK <= 256
#pragma unroll
    for (int o = 16; o > 0; o >>= 1) v += __shfl_down_sync(0xffffffffu, v, o);
    __shared__ int wsum[8];
    __shared__ int s_base;
    if (lane == 0) wsum[w] = v;
    __syncthreads();
    if (t == 0) {
        int s = 0;
#pragma unroll
        for (int j = 0; j < 8; j++) s += wsum[j];
        s_base = s;
    }
    __syncthreads();
    int idx = bid * SCAN_B + t;
    if (idx < NN) {
        g_row_start[idx] = g_scan_tmp[idx] + s_base;
        g_scale_out[idx] = rsqrtf(fmaxf((float)g_deg_out_i[idx], 1.0f));
    }
}

// ---------------------------------------------------------------------------
// 4) atomic-free scatter: perm[row_start[dst] + slot] = src
// ---------------------------------------------------------------------------
__global__ void scatter_kernel(const int* __restrict__ src, const int* __restrict__ dst) {
    int t = blockIdx.x * blockDim.x + threadIdx.x;
    int e0 = t * 4;
    if (e0 < NE) {
        int4 d  = *reinterpret_cast<const int4*>(dst + e0);
        int4 s  = *reinterpret_cast<const int4*>(src + e0);
        int4 sl = *reinterpret_cast<const int4*>(g_slot + e0);
        g_perm_src[g_row_start[d.x] + sl.x] = s.x;
        g_perm_src[g_row_start[d.y] + sl.y] = s.y;
        g_perm_src[g_row_start[d.z] + sl.z] = s.z;
        g_perm_src[g_row_start[d.w] + sl.w] = s.w;
    }
}

// ---------------------------------------------------------------------------
// 5) CSR aggregation (fp32 rows): one warp per node.
//    Indices fetched as int4 (vector broadcast) and double-batched -> 8 row
//    gathers in flight per lane; fp32 accumulate; both norms folded in.
// ---------------------------------------------------------------------------
__device__ __forceinline__ void fmacc(float4& acc, float c, const float4& a) {
    acc.x += c * a.x; acc.y += c * a.y; acc.z += c * a.z; acc.w += c * a.w;
}

__global__ void __launch_bounds__(256)
agg_kernel(const float* __restrict__ x) {
    int gtid = blockIdx.x * blockDim.x + threadIdx.x;
    int node = gtid >> 5;
    int lane = threadIdx.x & 31;
    if (node >= NN) return;

    int start = g_row_start[node];
    int len   = g_deg_in_i[node];
    int end   = start + len;
    const float4* x4 = reinterpret_cast<const float4*>(x);

    float4 acc = make_float4(0.f, 0.f, 0.f, 0.f);

    // head: align to int4 boundary
    int i = start;
    int head = (4 - (start & 3)) & 3;
    if (head > len) head = len;
    for (int j = 0; j < head; j++, i++) {
        int s0 = g_perm_src[i];
        fmacc(acc, g_scale_out[s0], x4[(size_t)s0 * 32 + lane]);
    }

    // main: two int4 index loads -> 8 rows in flight
    for (; i + 8 <= end; i += 8) {
        int4 ia = *reinterpret_cast<const int4*>(g_perm_src + i);
        int4 ib = *reinterpret_cast<const int4*>(g_perm_src + i + 4);
        float c0 = g_scale_out[ia.x], c1 = g_scale_out[ia.y];
        float c2 = g_scale_out[ia.z], c3 = g_scale_out[ia.w];
        float c4 = g_scale_out[ib.x], c5 = g_scale_out[ib.y];
        float c6 = g_scale_out[ib.z], c7 = g_scale_out[ib.w];
        float4 a0 = x4[(size_t)ia.x * 32 + lane];
        float4 a1 = x4[(size_t)ia.y * 32 + lane];
        float4 a2 = x4[(size_t)ia.z * 32 + lane];
        float4 a3 = x4[(size_t)ia.w * 32 + lane];
        float4 a4 = x4[(size_t)ib.x * 32 + lane];
        float4 a5 = x4[(size_t)ib.y * 32 + lane];
        float4 a6 = x4[(size_t)ib.z * 32 + lane];
        float4 a7 = x4[(size_t)ib.w * 32 + lane];
        fmacc(acc, c0, a0); fmacc(acc, c1, a1); fmacc(acc, c2, a2); fmacc(acc, c3, a3);
        fmacc(acc, c4, a4); fmacc(acc, c5, a5); fmacc(acc, c6, a6); fmacc(acc, c7, a7);
    }
    // mid: one int4 group
    if (i + 4 <= end) {
        int4 ia = *reinterpret_cast<const int4*>(g_perm_src + i);
        float c0 = g_scale_out[ia.x], c1 = g_scale_out[ia.y];
        float c2 = g_scale_out[ia.z], c3 = g_scale_out[ia.w];
        float4 a0 = x4[(size_t)ia.x * 32 + lane];
        float4 a1 = x4[(size_t)ia.y * 32 + lane];
        float4 a2 = x4[(size_t)ia.z * 32 + lane];
        float4 a3 = x4[(size_t)ia.w * 32 + lane];
        fmacc(acc, c0, a0); fmacc(acc, c1, a1); fmacc(acc, c2, a2); fmacc(acc, c3, a3);
        i += 4;
    }
    // tail
    for (; i < end; i++) {
        int s0 = g_perm_src[i];
        fmacc(acc, g_scale_out[s0], x4[(size_t)s0 * 32 + lane]);
    }

    float inv = rsqrtf(fmaxf((float)len, 1.0f));
    acc.x *= inv; acc.y *= inv; acc.z *= inv; acc.w *= inv;
    reinterpret_cast<float4*>(g_h + (size_t)node * F)[lane] = acc;
}

// ---------------------------------------------------------------------------
// 6) GEMM via 2-way fp16-split HMMA m16n8k16: out = h @ W + bias (R8-proven)
// ---------------------------------------------------------------------------
__device__ __forceinline__ void mma_f16(float& d0, float& d1, float& d2, float& d3,
                                        uint32_t a0, uint32_t a1, uint32_t a2, uint32_t a3,
                                        uint32_t b0, uint32_t b1) {
    asm volatile(
        "mma.sync.aligned.m16n8k16.row.col.f32.f16.f16.f32 "
        "{%0,%1,%2,%3}, {%4,%5,%6,%7}, {%8,%9}, {%0,%1,%2,%3};"
        : "+f"(d0), "+f"(d1), "+f"(d2), "+f"(d3)
        : "r"(a0), "r"(a1), "r"(a2), "r"(a3), "r"(b0), "r"(b1));
}

__device__ __forceinline__ void split2(float2 f, uint32_t& hi, uint32_t& lo) {
    half2 h = __floats2half2_rn(f.x, f.y);
    half2 l = __floats2half2_rn(f.x - __half2float(__low2half(h)),
                                f.y - __half2float(__high2half(h)));
    hi = h2u(h); lo = h2u(l);
}

__global__ void __launch_bounds__(GT, 2)
gemm_tc_kernel(const float* __restrict__ bias, float* __restrict__ out) {
    extern __shared__ float sm[];
    uint4* Wps = reinterpret_cast<uint4*>(sm);          // KSP*32*17 uint4
    float* Hs  = sm + KSP * 32 * WPAD * 4;              // BM * SW floats
    float* Bs  = Hs + BM * SW;                          // F floats

    int tid  = threadIdx.x;
    int row0 = blockIdx.x * BM;

    for (int i = tid; i < KSP * 32 * 16; i += GT) {
        int nt = i & 15, rest = i >> 4;
        Wps[rest * WPAD + nt] = g_Wpk[i];
    }
    for (int i = tid; i < BM * (F / 4); i += GT) {
        int r = i / (F / 4), c4 = i % (F / 4);
        float4 v = make_float4(0.f, 0.f, 0.f, 0.f);
        int grow = row0 + r;
        if (grow < NN)
            v = reinterpret_cast<const float4*>(g_h)[grow * (F / 4) + c4];
        reinterpret_cast<float4*>(&Hs[r * SW + c4 * 4])[0] = v;
    }
    if (tid < F) Bs[tid] = bias[tid];
    __syncthreads();

    int warp = tid >> 5;
    int lane = tid & 31;
    int g    = lane >> 2;
    int t    = lane & 3;
    int rb   = warp * 16;

    float d[16][4];
#pragma unroll
    for (int nt = 0; nt < 16; nt++)
#pragma unroll
        for (int j = 0; j < 4; j++) d[nt][j] = 0.f;

#pragma unroll
    for (int ks = 0; ks < KSP; ks++) {
        int k0 = ks * 16;
        float2 f00 = *reinterpret_cast<float2*>(&Hs[(rb + g)     * SW + k0 + 2 * t]);
        float2 f10 = *reinterpret_cast<float2*>(&Hs[(rb + g + 8) * SW + k0 + 2 * t]);
        float2 f01 = *reinterpret_cast<float2*>(&Hs[(rb + g)     * SW + k0 + 2 * t + 8]);
        float2 f11 = *reinterpret_cast<float2*>(&Hs[(rb + g + 8) * SW + k0 + 2 * t + 8]);
        uint32_t ah0, al0, ah1, al1, ah2, al2, ah3, al3;
        split2(f00, ah0, al0);
        split2(f10, ah1, al1);
        split2(f01, ah2, al2);
        split2(f11, ah3, al3);

        const uint4* wrow = &Wps[(ks * 32 + lane) * WPAD];
#pragma unroll
        for (int nt = 0; nt < 16; nt++) {
            uint4 wb = wrow[nt];
            mma_f16(d[nt][0], d[nt][1], d[nt][2], d[nt][3],
                    ah0, ah1, ah2, ah3, wb.x, wb.y);       // Ah*Bh
            mma_f16(d[nt][0], d[nt][1], d[nt][2], d[nt][3],
                    ah0, ah1, ah2, ah3, wb.z, wb.w);       // Ah*Bl
            mma_f16(d[nt][0], d[nt][1], d[nt][2], d[nt][3],
                    al0, al1, al2, al3, wb.x, wb.y);       // Al*Bh
        }
    }

    int rA = row0 + rb + g;
    int rB = rA + 8;
#pragma unroll
    for (int nt = 0; nt < 16; nt++) {
        int col = nt * 8 + t * 2;
        float b0 = Bs[col], b1 = Bs[col + 1];
        if (rA < NN) {
            float2 o = make_float2(d[nt][0] + b0, d[nt][1] + b1);
            reinterpret_cast<float2*>(out + (size_t)rA * F + col)[0] = o;
        }
        if (rB < NN) {
            float2 o = make_float2(d[nt][2] + b0, d[nt][3] + b1);
            reinterpret_cast<float2*>(out + (size_t)rB * F + col)[0] = o;
        }
    }
}

// ---------------------------------------------------------------------------
extern "C" void kernel_launch(void* const* d_in, const int* in_sizes, int n_in,
                              void* d_out, int out_size) {
    const float* x      = (const float*)d_in[0];
    const int*   src    = (const int*)d_in[1];
    const int*   dst    = (const int*)d_in[2];
    const float* weight = (const float*)d_in[3];
    const float* bias   = (const float*)d_in[4];
    float*       out    = (float*)d_out;

    init_kernel<<<(NN + 255) / 256, 256>>>(weight);
    deg_kernel<<<(NE / 2 + 255) / 256, 256>>>(src, dst);
    scan1_kernel<<<NBLK, SCAN_B>>>();
    scan3_kernel<<<NBLK, SCAN_B>>>();
    scatter_kernel<<<(NE / 4 + 255) / 256, 256>>>(src, dst);

    {
        long long threads = (long long)NN * 32;
        int blocks = (int)((threads + 255) / 256);
        agg_kernel<<<blocks, 256>>>(x);
    }
    {
        int smem = (KSP * 32 * WPAD * 4 + BM * SW + F) * (int)sizeof(float); // 103936 B
        cudaFuncSetAttribute(gemm_tc_kernel, cudaFuncAttributeMaxDynamicSharedMemorySize, smem);
        gemm_tc_kernel<<<(NN + BM - 1) / BM, GT, smem>>>(bias, out);
    }
}

// round 14
// speedup vs baseline: 1.0403x; 1.0142x over previous
#include <cuda_runtime.h>
#include <cuda_fp16.h>
#include <cstdint>

#define NN 50000
#define NE 800000
#define F  128
#define SCAN_B 256
#define NBLK ((NN + SCAN_B - 1) / SCAN_B)   // 196

#define BM   64           // gemm rows per block
#define GT   128          // gemm threads
#define SW   132          // Hs padded row stride (floats)
#define WPAD 17           // Wpk padded nt stride (uint4s)
#define KSP  8            // k-steps of 16

// ---------------- device scratch (no allocations allowed) -------------------
// zero-initialized at module load; gemm_tc_kernel re-zeroes deg arrays +
// counter at its start, so every call to kernel_launch sees them zeroed.
__device__ int   g_deg_out_i[NN];
__device__ int   g_deg_in_i[NN];
__device__ int   g_scan_counter;
__device__ int   g_row_start[NN];
__device__ float g_scale_out[NN];
__device__ int   g_slot[NE];
__device__ int   g_perm_src[NE + 8];       // +pad so int4 tail reads are safe
__device__ float g_h[NN * F];
__device__ uint4 g_Wpk[KSP * 32 * 16];     // fp16 frags {bh0,bh1,bl0,bl1}
__device__ int   g_block_sums[NBLK];

__device__ __forceinline__ uint32_t h2u(half2 h) {
    return *reinterpret_cast<uint32_t*>(&h);
}

// ---------------------------------------------------------------------------
// 1) degrees; in-degree atomic return value = edge slot
//    (deg arrays were zeroed by the previous call's gemm / module-load init)
// ---------------------------------------------------------------------------
__global__ void deg_kernel(const int* __restrict__ src, const int* __restrict__ dst) {
    int t = blockIdx.x * blockDim.x + threadIdx.x;
    int e0 = t * 2;
    if (e0 < NE) {
        int s0 = src[e0], s1 = src[e0 + 1];
        int d0 = dst[e0], d1 = dst[e0 + 1];
        atomicAdd(&g_deg_out_i[s0], 1);
        atomicAdd(&g_deg_out_i[s1], 1);
        g_slot[e0]     = atomicAdd(&g_deg_in_i[d0], 1);
        g_slot[e0 + 1] = atomicAdd(&g_deg_in_i[d1], 1);
    }
}

// ---------------------------------------------------------------------------
// 2) fused exclusive scan (single kernel, counter barrier) + W split
//    All 196 blocks are co-resident (4 blocks/SM x 148 SMs), so the
//    all-posted spin cannot deadlock.
// ---------------------------------------------------------------------------
__global__ void __launch_bounds__(SCAN_B)
scan_kernel(const float* __restrict__ weight) {
    int bid  = blockIdx.x;
    int t    = threadIdx.x;
    int gidx = bid * SCAN_B + t;
    int lane = t & 31;
    int w    = t >> 5;

    // ---- W split (independent; overlaps with scan/wait) ----
    if (gidx < KSP * 32 * 16) {
        int i    = gidx;
        int nt   = i & 15;
        int rest = i >> 4;
        int ln   = rest & 31;
        int ks   = rest >> 5;
        int tg   = ln & 3;
        int g    = ln >> 2;
        int k0 = ks * 16, n0 = nt * 8;
        float w00 = weight[(k0 + 2 * tg)     * F + n0 + g];
        float w01 = weight[(k0 + 2 * tg + 1) * F + n0 + g];
        float w10 = weight[(k0 + 2 * tg + 8) * F + n0 + g];
        float w11 = weight[(k0 + 2 * tg + 9) * F + n0 + g];
        half2 h0 = __floats2half2_rn(w00, w01);
        half2 h1 = __floats2half2_rn(w10, w11);
        half2 l0 = __floats2half2_rn(w00 - __half2float(__low2half(h0)),
                                     w01 - __half2float(__high2half(h0)));
        half2 l1 = __floats2half2_rn(w10 - __half2float(__low2half(h1)),
                                     w11 - __half2float(__high2half(h1)));
        g_Wpk[i] = make_uint4(h2u(h0), h2u(h1), h2u(l0), h2u(l1));
    }

    // ---- phase 1: local block scan of deg_in ----
    int v = (gidx < NN) ? g_deg_in_i[gidx] : 0;
    int x = v;
#pragma unroll
    for (int o = 1; o < 32; o <<= 1) {
        int tt = __shfl_up_sync(0xffffffffu, x, o);
        if (lane >= o) x += tt;
    }
    __shared__ int wsum[8];
    __shared__ int s_base;
    if (lane == 31) wsum[w] = x;
    __syncthreads();
    if (t < 8) {
        int s = wsum[t];
#pragma unroll
        for (int o = 1; o < 8; o <<= 1) {
            int tt = __shfl_up_sync(0xffu, s, o);
            if (t >= o) s += tt;
        }
        wsum[t] = s;
    }
    __syncthreads();
    int woff = (w > 0) ? wsum[w - 1] : 0;
    int excl = woff + x - v;          // exclusive within block
    if (t == 0) {
        g_block_sums[bid] = wsum[7];  // block total
        __threadfence();              // release
        atomicAdd(&g_scan_counter, 1);
    }

    // ---- barrier: wait until all blocks posted ----
    if (t == 0) {
        while (atomicAdd(&g_scan_counter, 0) < NBLK) { }
    }
    __syncthreads();
    __threadfence();                  // acquire

    // ---- phase 2: reduce preceding block sums ----
    int pv = (t < bid) ? g_block_sums[t] : 0;   // NBLK <= 256
#pragma unroll
    for (int o = 16; o > 0; o >>= 1) pv += __shfl_down_sync(0xffffffffu, pv, o);
    __syncthreads();                  // wsum reuse hazard
    if (lane == 0) wsum[w] = pv;
    __syncthreads();
    if (t == 0) {
        int s = 0;
#pragma unroll
        for (int j = 0; j < 8; j++) s += wsum[j];
        s_base = s;
    }
    __syncthreads();
    if (gidx < NN) {
        g_row_start[gidx] = excl + s_base;
        g_scale_out[gidx] = rsqrtf(fmaxf((float)g_deg_out_i[gidx], 1.0f));
    }
}

// ---------------------------------------------------------------------------
// 3) atomic-free scatter: perm[row_start[dst] + slot] = src
// ---------------------------------------------------------------------------
__global__ void scatter_kernel(const int* __restrict__ src, const int* __restrict__ dst) {
    int t = blockIdx.x * blockDim.x + threadIdx.x;
    int e0 = t * 4;
    if (e0 < NE) {
        int4 d  = *reinterpret_cast<const int4*>(dst + e0);
        int4 s  = *reinterpret_cast<const int4*>(src + e0);
        int4 sl = *reinterpret_cast<const int4*>(g_slot + e0);
        g_perm_src[g_row_start[d.x] + sl.x] = s.x;
        g_perm_src[g_row_start[d.y] + sl.y] = s.y;
        g_perm_src[g_row_start[d.z] + sl.z] = s.z;
        g_perm_src[g_row_start[d.w] + sl.w] = s.w;
    }
}

// ---------------------------------------------------------------------------
// 4) CSR aggregation (fp32 rows): one warp per node; int4 index batching.
// ---------------------------------------------------------------------------
__device__ __forceinline__ void fmacc(float4& acc, float c, const float4& a) {
    acc.x += c * a.x; acc.y += c * a.y; acc.z += c * a.z; acc.w += c * a.w;
}

__global__ void __launch_bounds__(256)
agg_kernel(const float* __restrict__ x) {
    int gtid = blockIdx.x * blockDim.x + threadIdx.x;
    int node = gtid >> 5;
    int lane = threadIdx.x & 31;
    if (node >= NN) return;

    int start = g_row_start[node];
    int len   = g_deg_in_i[node];
    int end   = start + len;
    const float4* x4 = reinterpret_cast<const float4*>(x);

    float4 acc = make_float4(0.f, 0.f, 0.f, 0.f);

    int i = start;
    int head = (4 - (start & 3)) & 3;
    if (head > len) head = len;
    for (int j = 0; j < head; j++, i++) {
        int s0 = g_perm_src[i];
        fmacc(acc, g_scale_out[s0], x4[(size_t)s0 * 32 + lane]);
    }
    for (; i + 8 <= end; i += 8) {
        int4 ia = *reinterpret_cast<const int4*>(g_perm_src + i);
        int4 ib = *reinterpret_cast<const int4*>(g_perm_src + i + 4);
        float c0 = g_scale_out[ia.x], c1 = g_scale_out[ia.y];
        float c2 = g_scale_out[ia.z], c3 = g_scale_out[ia.w];
        float c4 = g_scale_out[ib.x], c5 = g_scale_out[ib.y];
        float c6 = g_scale_out[ib.z], c7 = g_scale_out[ib.w];
        float4 a0 = x4[(size_t)ia.x * 32 + lane];
        float4 a1 = x4[(size_t)ia.y * 32 + lane];
        float4 a2 = x4[(size_t)ia.z * 32 + lane];
        float4 a3 = x4[(size_t)ia.w * 32 + lane];
        float4 a4 = x4[(size_t)ib.x * 32 + lane];
        float4 a5 = x4[(size_t)ib.y * 32 + lane];
        float4 a6 = x4[(size_t)ib.z * 32 + lane];
        float4 a7 = x4[(size_t)ib.w * 32 + lane];
        fmacc(acc, c0, a0); fmacc(acc, c1, a1); fmacc(acc, c2, a2); fmacc(acc, c3, a3);
        fmacc(acc, c4, a4); fmacc(acc, c5, a5); fmacc(acc, c6, a6); fmacc(acc, c7, a7);
    }
    if (i + 4 <= end) {
        int4 ia = *reinterpret_cast<const int4*>(g_perm_src + i);
        float c0 = g_scale_out[ia.x], c1 = g_scale_out[ia.y];
        float c2 = g_scale_out[ia.z], c3 = g_scale_out[ia.w];
        float4 a0 = x4[(size_t)ia.x * 32 + lane];
        float4 a1 = x4[(size_t)ia.y * 32 + lane];
        float4 a2 = x4[(size_t)ia.z * 32 + lane];
        float4 a3 = x4[(size_t)ia.w * 32 + lane];
        fmacc(acc, c0, a0); fmacc(acc, c1, a1); fmacc(acc, c2, a2); fmacc(acc, c3, a3);
        i += 4;
    }
    for (; i < end; i++) {
        int s0 = g_perm_src[i];
        fmacc(acc, g_scale_out[s0], x4[(size_t)s0 * 32 + lane]);
    }

    float inv = rsqrtf(fmaxf((float)len, 1.0f));
    acc.x *= inv; acc.y *= inv; acc.z *= inv; acc.w *= inv;
    reinterpret_cast<float4*>(g_h + (size_t)node * F)[lane] = acc;
}

// ---------------------------------------------------------------------------
// 5) GEMM via 2-way fp16-split HMMA m16n8k16 + epilogue bias.
//    Also re-zeroes deg arrays + scan counter for the next call (the degrees
//    are dead after agg; grid covers 782*128 = 100096 >= NN threads).
// ---------------------------------------------------------------------------
__device__ __forceinline__ void mma_f16(float& d0, float& d1, float& d2, float& d3,
                                        uint32_t a0, uint32_t a1, uint32_t a2, uint32_t a3,
                                        uint32_t b0, uint32_t b1) {
    asm volatile(
        "mma.sync.aligned.m16n8k16.row.col.f32.f16.f16.f32 "
        "{%0,%1,%2,%3}, {%4,%5,%6,%7}, {%8,%9}, {%0,%1,%2,%3};"
        : "+f"(d0), "+f"(d1), "+f"(d2), "+f"(d3)
        : "r"(a0), "r"(a1), "r"(a2), "r"(a3), "r"(b0), "r"(b1));
}

__device__ __forceinline__ void split2(float2 f, uint32_t& hi, uint32_t& lo) {
    half2 h = __floats2half2_rn(f.x, f.y);
    half2 l = __floats2half2_rn(f.x - __half2float(__low2half(h)),
                                f.y - __half2float(__high2half(h)));
    hi = h2u(h); lo = h2u(l);
}

__global__ void __launch_bounds__(GT, 2)
gemm_tc_kernel(const float* __restrict__ bias, float* __restrict__ out) {
    extern __shared__ float sm[];
    uint4* Wps = reinterpret_cast<uint4*>(sm);          // KSP*32*17 uint4
    float* Hs  = sm + KSP * 32 * WPAD * 4;              // BM * SW floats
    float* Bs  = Hs + BM * SW;                          // F floats

    int tid  = threadIdx.x;
    int row0 = blockIdx.x * BM;

    // re-zero degree arrays + counter for the next kernel_launch call
    {
        int gz = blockIdx.x * GT + tid;
        if (gz < NN) { g_deg_out_i[gz] = 0; g_deg_in_i[gz] = 0; }
        if (gz == 0) g_scan_counter = 0;
    }

    for (int i = tid; i < KSP * 32 * 16; i += GT) {
        int nt = i & 15, rest = i >> 4;
        Wps[rest * WPAD + nt] = g_Wpk[i];
    }
    for (int i = tid; i < BM * (F / 4); i += GT) {
        int r = i / (F / 4), c4 = i % (F / 4);
        float4 v = make_float4(0.f, 0.f, 0.f, 0.f);
        int grow = row0 + r;
        if (grow < NN)
            v = reinterpret_cast<const float4*>(g_h)[grow * (F / 4) + c4];
        reinterpret_cast<float4*>(&Hs[r * SW + c4 * 4])[0] = v;
    }
    if (tid < F) Bs[tid] = bias[tid];
    __syncthreads();

    int warp = tid >> 5;
    int lane = tid & 31;
    int g    = lane >> 2;
    int t    = lane & 3;
    int rb   = warp * 16;

    float d[16][4];
#pragma unroll
    for (int nt = 0; nt < 16; nt++)
#pragma unroll
        for (int j = 0; j < 4; j++) d[nt][j] = 0.f;

#pragma unroll
    for (int ks = 0; ks < KSP; ks++) {
        int k0 = ks * 16;
        float2 f00 = *reinterpret_cast<float2*>(&Hs[(rb + g)     * SW + k0 + 2 * t]);
        float2 f10 = *reinterpret_cast<float2*>(&Hs[(rb + g + 8) * SW + k0 + 2 * t]);
        float2 f01 = *reinterpret_cast<float2*>(&Hs[(rb + g)     * SW + k0 + 2 * t + 8]);
        float2 f11 = *reinterpret_cast<float2*>(&Hs[(rb + g + 8) * SW + k0 + 2 * t + 8]);
        uint32_t ah0, al0, ah1, al1, ah2, al2, ah3, al3;
        split2(f00, ah0, al0);
        split2(f10, ah1, al1);
        split2(f01, ah2, al2);
        split2(f11, ah3, al3);

        const uint4* wrow = &Wps[(ks * 32 + lane) * WPAD];
#pragma unroll
        for (int nt = 0; nt < 16; nt++) {
            uint4 wb = wrow[nt];
            mma_f16(d[nt][0], d[nt][1], d[nt][2], d[nt][3],
                    ah0, ah1, ah2, ah3, wb.x, wb.y);       // Ah*Bh
            mma_f16(d[nt][0], d[nt][1], d[nt][2], d[nt][3],
                    ah0, ah1, ah2, ah3, wb.z, wb.w);       // Ah*Bl
            mma_f16(d[nt][0], d[nt][1], d[nt][2], d[nt][3],
                    al0, al1, al2, al3, wb.x, wb.y);       // Al*Bh
        }
    }

    int rA = row0 + rb + g;
    int rB = rA + 8;
#pragma unroll
    for (int nt = 0; nt < 16; nt++) {
        int col = nt * 8 + t * 2;
        float b0 = Bs[col], b1 = Bs[col + 1];
        if (rA < NN) {
            float2 o = make_float2(d[nt][0] + b0, d[nt][1] + b1);
            reinterpret_cast<float2*>(out + (size_t)rA * F + col)[0] = o;
        }
        if (rB < NN) {
            float2 o = make_float2(d[nt][2] + b0, d[nt][3] + b1);
            reinterpret_cast<float2*>(out + (size_t)rB * F + col)[0] = o;
        }
    }
}

// ---------------------------------------------------------------------------
extern "C" void kernel_launch(void* const* d_in, const int* in_sizes, int n_in,
                              void* d_out, int out_size) {
    const float* x      = (const float*)d_in[0];
    const int*   src    = (const int*)d_in[1];
    const int*   dst    = (const int*)d_in[2];
    const float* weight = (const float*)d_in[3];
    const float* bias   = (const float*)d_in[4];
    float*       out    = (float*)d_out;

    deg_kernel<<<(NE / 2 + 255) / 256, 256>>>(src, dst);
    scan_kernel<<<NBLK, SCAN_B>>>(weight);
    scatter_kernel<<<(NE / 4 + 255) / 256, 256>>>(src, dst);

    {
        long long threads = (long long)NN * 32;
        int blocks = (int)((threads + 255) / 256);
        agg_kernel<<<blocks, 256>>>(x);
    }
    {
        int smem = (KSP * 32 * WPAD * 4 + BM * SW + F) * (int)sizeof(float); // 103936 B
        cudaFuncSetAttribute(gemm_tc_kernel, cudaFuncAttributeMaxDynamicSharedMemorySize, smem);
        gemm_tc_kernel<<<(NN + BM - 1) / BM, GT, smem>>>(bias, out);
    }
}